// round 10
// baseline (speedup 1.0000x reference)
#include <cuda_runtime.h>

// x: (B=8, ns=4, D=512, nc=64) fp32
// out: concat(map_hidden, map_mask), each (B, D, 4, 64, 65) fp32.
// For rel in 0..3, base=1<<rel:
//   out[b,d,rel,i,j] = max(x[b,rel,d, i .. i+k-1]) where k=(j-i)/base,
//   valid when i%base==0, (j-i)%base==0, i<j<64. Mask = 1.0 at hits.
//
// Pure store-bound (~545 MB out). Round-6 structure (grid = bd x rel,
// fused hidden+mask, templated REL) with 256-bit stores (st.global.v8.b32,
// sm_100+): half the store instructions per byte.

#define B_DIM 8
#define D_DIM 512
#define NC 64
#define NJ 65
#define REGION (4 * NC * NJ)        // 16640 floats per half per (b,d)
#define RELBLK (NC * NJ)            // 4160 floats per rel block
#define NCHK8 (RELBLK / 8)          // 520 v8 chunks per rel block

__device__ __forceinline__ void stg256(float* p, const float* v) {
    asm volatile(
        "st.global.v8.b32 [%0], {%1,%2,%3,%4,%5,%6,%7,%8};"
        :: "l"(p),
           "r"(__float_as_uint(v[0])), "r"(__float_as_uint(v[1])),
           "r"(__float_as_uint(v[2])), "r"(__float_as_uint(v[3])),
           "r"(__float_as_uint(v[4])), "r"(__float_as_uint(v[5])),
           "r"(__float_as_uint(v[6])), "r"(__float_as_uint(v[7]))
        : "memory");
}

template<int REL>
__device__ __forceinline__ void prop3d_rel(
    const float* __restrict__ xrow,     // x[b, REL, d, :]
    float* __restrict__ hid,            // out + bd*REGION + REL*RELBLK
    float* __restrict__ msk,            // hid + half_elems
    float* __restrict__ Sp,             // shared, (64>>REL)^2 words
    float* __restrict__ xsh,            // shared, 64 words
    int tid)
{
    constexpr int W  = NC >> REL;       // table rows / row width
    constexpr int BM = (1 << REL) - 1;

    // ---- stage input row ----
    if (tid < NC) xsh[tid] = xrow[tid];
    __syncthreads();

    // ---- build running-max rows: i = r<<REL ----
    if (tid < W) {
        int i  = tid << REL;
        int bo = tid * W;
        int emax = (i + W < NC) ? (i + W) : NC;
        float m = xsh[i];
        Sp[bo] = m;
        #pragma unroll 4
        for (int e = i + 1; e < emax; e++) {
            m = fmaxf(m, xsh[e]);
            Sp[bo + (e - i)] = m;
        }
    }
    __syncthreads();

    // ---- write loop: 520 v8 chunks (32 B each) over this rel block ----
    for (int q = tid; q < NCHK8; q += 256) {
        int er = q << 3;                // element offset within rel block
        int i  = er / 65;               // const divisor -> mulhi
        int j  = er - i * 65;

        float hv[8], mv[8];

        #pragma unroll
        for (int l = 0; l < 8; l++) {
            int jj = j + l;
            int ii = i;
            if (jj >= NJ) { jj -= NJ; ii += 1; }   // one row wrap max (j+7 < 2*65)
            int diff = jj - ii;
            bool hit = (diff > 0) & (jj < NC);
            if (REL > 0) hit = hit & (((ii | diff) & BM) == 0);
            float h = 0.0f, m = 0.0f;
            if (hit) {
                h = Sp[(ii >> REL) * W + (diff >> REL) - 1];
                m = 1.0f;
            }
            hv[l] = h;
            mv[l] = m;
        }

        stg256(hid + er, hv);
        stg256(msk + er, mv);
    }
}

__global__ __launch_bounds__(256, 1)
void prop3d_kernel(const float* __restrict__ x, float* __restrict__ out,
                   long half_elems) {
    __shared__ float xsh[NC];
    __shared__ float Sp[4096];          // rel0 worst case: 64x64 (16 KB)

    const int bid = blockIdx.x;
    const int bd  = bid >> 2;           // b*512 + d
    const int rel = bid & 3;
    const int b   = bd >> 9;
    const int d   = bd & 511;
    const int tid = threadIdx.x;

    const float* xrow = x + ((((long)(b << 2) + rel) * D_DIM) + d) * NC;
    float* hid = out + (long)bd * REGION + rel * RELBLK;
    float* msk = hid + half_elems;

    switch (rel) {
        case 0:  prop3d_rel<0>(xrow, hid, msk, Sp, xsh, tid); break;
        case 1:  prop3d_rel<1>(xrow, hid, msk, Sp, xsh, tid); break;
        case 2:  prop3d_rel<2>(xrow, hid, msk, Sp, xsh, tid); break;
        default: prop3d_rel<3>(xrow, hid, msk, Sp, xsh, tid); break;
    }
}

extern "C" void kernel_launch(void* const* d_in, const int* in_sizes, int n_in,
                              void* d_out, int out_size) {
    const float* x = (const float*)d_in[0];
    float* out = (float*)d_out;
    long half = (long)out_size / 2;     // map_hidden elements; map_mask follows

    prop3d_kernel<<<B_DIM * D_DIM * 4, 256>>>(x, out, half);
}